// round 15
// baseline (speedup 1.0000x reference)
#include <cuda_runtime.h>
#include <cuda_fp16.h>
#include <math.h>
#include <stdint.h>

// Problem constants
#define M_TOK   8192
#define D_IN    4096
#define Z_DIM   1024
#define D_OUT   4096
#define CAT_DIM 5120
#define LN_EPS  1e-5f

#define MU_OFF  (M_TOK * (size_t)D_OUT)
#define STD_OFF (MU_OFF + (size_t)M_TOK * Z_DIM)

// Scratch (device globals — allocation-free per harness rules)
__device__ __align__(256) float  g_c[(size_t)M_TOK * Z_DIM];      // pre-LN (fp32)
__device__ __align__(256) __half g_h[(size_t)M_TOK * Z_DIM];      // post LN+tanh (fp16)
__device__ __align__(256) __half g_cat[(size_t)M_TOK * CAT_DIM];  // tanh concat (fp16)
__device__ __align__(256) __half g_x16[(size_t)M_TOK * D_IN];     // x in fp16
// fp16 weights, packed: W1 | W2 | [Wmu/Wls row-interleaved] | Wzw
#define W1_OFF  0
#define W2_OFF  4194304
#define WMU_OFF 5242880            // interleaved mu/ls occupies 2M halfs here
#define WZW_OFF 7340032
#define W_TOTAL 28311552
__device__ __align__(256) __half g_w16[(size_t)W_TOTAL];

// ---------------------------------------------------------------------------
// PTX helpers
// ---------------------------------------------------------------------------
__device__ __forceinline__ void cp16(uint32_t dst, const void* src) {
    asm volatile("cp.async.cg.shared.global [%0], [%1], 16;\n" :: "r"(dst), "l"(src));
}
__device__ __forceinline__ void cp_commit() {
    asm volatile("cp.async.commit_group;\n" ::: "memory");
}
__device__ __forceinline__ void cp_wait2() {
    asm volatile("cp.async.wait_group 2;\n" ::: "memory");
}
__device__ __forceinline__ void ldsm4(uint32_t* r, uint32_t addr) {
    asm volatile("ldmatrix.sync.aligned.m8n8.x4.shared.b16 {%0,%1,%2,%3}, [%4];\n"
        : "=r"(r[0]), "=r"(r[1]), "=r"(r[2]), "=r"(r[3]) : "r"(addr));
}
__device__ __forceinline__ void mma_f16(float* d, const uint32_t* a, const uint32_t* b) {
    asm volatile(
        "mma.sync.aligned.m16n8k16.row.col.f32.f16.f16.f32 "
        "{%0,%1,%2,%3}, {%4,%5,%6,%7}, {%8,%9}, {%0,%1,%2,%3};\n"
        : "+f"(d[0]), "+f"(d[1]), "+f"(d[2]), "+f"(d[3])
        : "r"(a[0]), "r"(a[1]), "r"(a[2]), "r"(a[3]), "r"(b[0]), "r"(b[1]));
}

// Fast, accurate tanh: 1 - 2/(e^{2x}+1) via MUFU.EX2 + MUFU.RCP.
__device__ __forceinline__ float fast_tanh(float x) {
    float e = __expf(2.0f * x);
    return 1.0f - 2.0f / (e + 1.0f);
}

// ---------------------------------------------------------------------------
// fp16 tensor-core GEMM (R9/R12-verified mainloop — do not touch):
// Block tile 256x128, BK=32 halfs, 4-stage cp.async, single sync per k-tile,
// 512 threads, 16 warps (4M x 4N), warp tile 64x32.
// mode 0: C = A*B^T + biasA (fp32, stride N).
// mode 3: B rows are interleaved [Wmu_i; Wls_i]; per column pair (even,odd):
//         mu = v_even + bmu[zc]; ls = v_odd + bls[zc]; std = exp(0.5 ls);
//         C[r,zc]=mu (stride Z), C2[r,zc]=std (stride Z),
//         catp[r, zc] = fp16(tanh(eps[r,zc]*std + mu)).
// ---------------------------------------------------------------------------
#define GBK 32
#define STAGE_BYTES 24576
#define B_OFF       16384
#define STAGES      4
#define GEMM_SMEM   (STAGES * STAGE_BYTES)    // 96 KB

__global__ void __launch_bounds__(512, 1)
gemm_f16_kernel(const __half* __restrict__ A, const __half* __restrict__ B,
                const float* __restrict__ biasA, const float* __restrict__ biasB,
                float* __restrict__ C, float* __restrict__ C2,
                const float* __restrict__ eps, __half* __restrict__ catp,
                int M, int N, int K, int mode)
{
    extern __shared__ __align__(128) char smem[];

    const int tid  = threadIdx.x;
    const int lane = tid & 31;
    const int warp = tid >> 5;
    const int warp_m = warp & 3;
    const int warp_n = warp >> 2;

    const int bm = blockIdx.y * 256;
    const int bn = blockIdx.x * 128;

    const uint32_t sm_base = (uint32_t)__cvta_generic_to_shared(smem);

    const int a_row = tid >> 1;
    const int a_c0  = (tid & 1) * 2;
    const int a_swz = (a_row >> 1) & 3;
    const __half* Ag = A + (size_t)(bm + a_row) * K + a_c0 * 8;
    uint32_t a_dst[2];
#pragma unroll
    for (int i = 0; i < 2; i++)
        a_dst[i] = sm_base + (uint32_t)(a_row * 64 + (((a_c0 + i) ^ a_swz) << 4));
    const int b_row = tid >> 2;
    const int b_c   = tid & 3;
    const int b_swz = (b_row >> 1) & 3;
    const __half* Bg = B + (size_t)(bn + b_row) * K + b_c * 8;
    const uint32_t b_dst = sm_base + B_OFF +
        (uint32_t)(b_row * 64 + ((b_c ^ b_swz) << 4));

    const int sa   = (lane & 7) + ((lane >> 3) & 1) * 8;
    const int hiA  = (lane >> 4) & 1;
    const int aswz = (sa >> 1) & 3;
    uint32_t a_base[4];
#pragma unroll
    for (int mf = 0; mf < 4; mf++)
        a_base[mf] = sm_base + (uint32_t)(warp_m * 64 + mf * 16 + sa) * 64u;

    const int hiB  = (lane >> 3) & 1;
    const int nbr  = ((lane >> 4) & 1) * 8 + (lane & 7);
    const int bswz = (nbr >> 1) & 3;
    uint32_t b_base[2];
#pragma unroll
    for (int p = 0; p < 2; p++)
        b_base[p] = sm_base + B_OFF + (uint32_t)(warp_n * 32 + p * 16 + nbr) * 64u;

    // ---- bias preload
    float bias2[4][2];
#pragma unroll
    for (int nf = 0; nf < 4; nf++) {
        int col = bn + warp_n * 32 + nf * 8 + (lane & 3) * 2;
        if (mode == 3) {
            int zc = col >> 1;               // col even; pair (mu, ls) at z-col zc
            bias2[nf][0] = __ldg(biasA + zc);   // bmu
            bias2[nf][1] = __ldg(biasB + zc);   // bls
        } else {
            bias2[nf][0] = __ldg(biasA + col);
            bias2[nf][1] = __ldg(biasA + col + 1);
        }
    }

    float acc[4][4][4];
#pragma unroll
    for (int mf = 0; mf < 4; mf++)
#pragma unroll
        for (int nf = 0; nf < 4; nf++)
#pragma unroll
            for (int r = 0; r < 4; r++) acc[mf][nf][r] = 0.f;

    const int KT = K / GBK;

#pragma unroll
    for (int s = 0; s < STAGES - 1; s++) {
        if (s < KT) {
            const __half* ap = Ag + s * GBK;
            const __half* bq = Bg + s * GBK;
            uint32_t so = (uint32_t)s * STAGE_BYTES;
            cp16(a_dst[0] + so, ap);
            cp16(a_dst[1] + so, ap + 8);
            cp16(b_dst + so, bq);
        }
        cp_commit();
    }

    for (int kt = 0; kt < KT; kt++) {
        cp_wait2();
        __syncthreads();

        {
            int nxt = kt + (STAGES - 1);
            if (nxt < KT) {
                int sn = nxt & (STAGES - 1);
                const __half* ap = Ag + nxt * GBK;
                const __half* bq = Bg + nxt * GBK;
                uint32_t so = (uint32_t)sn * STAGE_BYTES;
                cp16(a_dst[0] + so, ap);
                cp16(a_dst[1] + so, ap + 8);
                cp16(b_dst + so, bq);
            }
            cp_commit();
        }

        const uint32_t so = (uint32_t)(kt & (STAGES - 1)) * STAGE_BYTES;
#pragma unroll
        for (int kk = 0; kk < 2; kk++) {
            uint32_t a[4][4];
#pragma unroll
            for (int mf = 0; mf < 4; mf++)
                ldsm4(a[mf], a_base[mf] + so + (uint32_t)(((kk * 2 + hiA) ^ aswz) << 4));
            uint32_t b[4][2];
#pragma unroll
            for (int p = 0; p < 2; p++) {
                uint32_t r[4];
                ldsm4(r, b_base[p] + so + (uint32_t)(((kk * 2 + hiB) ^ bswz) << 4));
                b[2 * p][0] = r[0]; b[2 * p][1] = r[1];
                b[2 * p + 1][0] = r[2]; b[2 * p + 1][1] = r[3];
            }
#pragma unroll
            for (int mf = 0; mf < 4; mf++)
#pragma unroll
                for (int nf = 0; nf < 4; nf++)
                    mma_f16(acc[mf][nf], a[mf], b[nf]);
        }
    }

    // ---- epilogue
#pragma unroll
    for (int mf = 0; mf < 4; mf++) {
        int r0 = bm + warp_m * 64 + mf * 16 + (lane >> 2);
#pragma unroll
        for (int nf = 0; nf < 4; nf++) {
            int col = bn + warp_n * 32 + nf * 8 + (lane & 3) * 2;
            float v0 = acc[mf][nf][0] + bias2[nf][0];
            float v1 = acc[mf][nf][1] + bias2[nf][1];
            float v2 = acc[mf][nf][2] + bias2[nf][0];
            float v3 = acc[mf][nf][3] + bias2[nf][1];
            if (mode == 3) {
                // v0/v2 = mu (rows r0, r0+8); v1/v3 = logsigma
                int zc = col >> 1;
                float sd0 = __expf(0.5f * v1);
                float sd1 = __expf(0.5f * v3);
                size_t i0 = (size_t)r0 * Z_DIM + zc;
                size_t i1 = (size_t)(r0 + 8) * Z_DIM + zc;
                C[i0]  = v0;  C[i1]  = v2;    // mu
                C2[i0] = sd0; C2[i1] = sd1;   // std
                float z0 = __ldg(eps + i0) * sd0 + v0;
                float z1 = __ldg(eps + i1) * sd1 + v2;
                catp[(size_t)r0 * CAT_DIM + zc]       = __float2half_rn(fast_tanh(z0));
                catp[(size_t)(r0 + 8) * CAT_DIM + zc] = __float2half_rn(fast_tanh(z1));
            } else {
                *(float2*)(C + (size_t)r0 * N + col) = make_float2(v0, v1);
                *(float2*)(C + (size_t)(r0 + 8) * N + col) = make_float2(v2, v3);
            }
        }
    }
}

// ---------------------------------------------------------------------------
// x prep: x16 = fp16(x) AND cat[:,Z_DIM:] = fp16(tanh(x)). 8 elems/thread.
// ---------------------------------------------------------------------------
__global__ void __launch_bounds__(256)
x_prep_kernel(const float* __restrict__ x, __half* __restrict__ x16,
              __half* __restrict__ cat, size_t n8)
{
    size_t i = (size_t)blockIdx.x * blockDim.x + threadIdx.x;
    if (i >= n8) return;
    size_t e = i * 8;
    float4 v0 = *(const float4*)(x + e);
    float4 v1 = *(const float4*)(x + e + 4);
    __half2 h0 = __floats2half2_rn(v0.x, v0.y);
    __half2 h1 = __floats2half2_rn(v0.z, v0.w);
    __half2 h2 = __floats2half2_rn(v1.x, v1.y);
    __half2 h3 = __floats2half2_rn(v1.z, v1.w);
    uint4 o;
    o.x = *(uint32_t*)&h0; o.y = *(uint32_t*)&h1;
    o.z = *(uint32_t*)&h2; o.w = *(uint32_t*)&h3;
    *(uint4*)(x16 + e) = o;

    __half2 t0 = __floats2half2_rn(fast_tanh(v0.x), fast_tanh(v0.y));
    __half2 t1 = __floats2half2_rn(fast_tanh(v0.z), fast_tanh(v0.w));
    __half2 t2 = __floats2half2_rn(fast_tanh(v1.x), fast_tanh(v1.y));
    __half2 t3 = __floats2half2_rn(fast_tanh(v1.z), fast_tanh(v1.w));
    uint4 t;
    t.x = *(uint32_t*)&t0; t.y = *(uint32_t*)&t1;
    t.z = *(uint32_t*)&t2; t.w = *(uint32_t*)&t3;
    size_t row = e >> 12;                 // / D_IN
    int col = (int)(e & (D_IN - 1));
    *(uint4*)(cat + row * CAT_DIM + Z_DIM + col) = t;
}

// ---------------------------------------------------------------------------
// Segmented weight convert (one launch). Wmu/Wls are ROW-INTERLEAVED into the
// WMU_OFF region: dst row 2i = Wmu row i, dst row 2i+1 = Wls row i.
// Block ranges (256 thr x 8 elems = 2048 elems/block):
//   W1  : blocks [0,2048)   W2: [2048,2560)  Wmu: [2560,3072)
//   Wls : [3072,3584)       Wzw: [3584,13824)
// ---------------------------------------------------------------------------
#define WCVT_BLOCKS 13824

__global__ void __launch_bounds__(256)
wcvt_kernel(const float* __restrict__ W1, const float* __restrict__ W2,
            const float* __restrict__ Wmu, const float* __restrict__ Wls,
            const float* __restrict__ Wzw, __half* __restrict__ w16)
{
    int bid = blockIdx.x;
    const float* src;
    __half* dst;
    int lb;
    int ilv = 0;   // 0: linear, 1: interleave even rows, 2: interleave odd rows
    if (bid < 2048)      { src = W1;  dst = w16 + W1_OFF;  lb = bid; }
    else if (bid < 2560) { src = W2;  dst = w16 + W2_OFF;  lb = bid - 2048; }
    else if (bid < 3072) { src = Wmu; dst = w16 + WMU_OFF; lb = bid - 2560; ilv = 1; }
    else if (bid < 3584) { src = Wls; dst = w16 + WMU_OFF; lb = bid - 3072; ilv = 2; }
    else                 { src = Wzw; dst = w16 + WZW_OFF; lb = bid - 3584; }

    size_t e = ((size_t)lb * 256 + threadIdx.x) * 8;
    float4 v0 = *(const float4*)(src + e);
    float4 v1 = *(const float4*)(src + e + 4);
    __half2 h0 = __floats2half2_rn(v0.x, v0.y);
    __half2 h1 = __floats2half2_rn(v0.z, v0.w);
    __half2 h2 = __floats2half2_rn(v1.x, v1.y);
    __half2 h3 = __floats2half2_rn(v1.z, v1.w);
    uint4 o;
    o.x = *(uint32_t*)&h0; o.y = *(uint32_t*)&h1;
    o.z = *(uint32_t*)&h2; o.w = *(uint32_t*)&h3;
    size_t de = e;
    if (ilv) {
        // src row = e>>10 (K=1024), dst row = 2*row (+1 for Wls)
        size_t row = e >> 10;
        int col = (int)(e & 1023);
        de = ((row << 1) + (ilv - 1)) * 1024 + col;
    }
    *(uint4*)(dst + de) = o;
}

// ---------------------------------------------------------------------------
// LayerNorm (1024) + tanh — WARP-PER-ROW, barrier-free.
// 256 threads = 8 warps = 8 rows per block; lane handles 8 strided float4s.
// Single-pass variance (E[x^2]-mu^2), butterfly shuffle reduction.
// ---------------------------------------------------------------------------
__global__ void __launch_bounds__(256)
ln_tanh_kernel(const float* __restrict__ in, const float* __restrict__ gamma,
               const float* __restrict__ beta, __half* __restrict__ out)
{
    const int lane = threadIdx.x & 31;
    const int wrp  = threadIdx.x >> 5;
    const int row  = blockIdx.x * 8 + wrp;
    const float* p = in + (size_t)row * Z_DIM;

    float4 v[8];
    float s1 = 0.f, s2 = 0.f;
#pragma unroll
    for (int j = 0; j < 8; j++) {
        v[j] = *(const float4*)(p + lane * 4 + j * 128);
        s1 += v[j].x + v[j].y + v[j].z + v[j].w;
        s2 += v[j].x * v[j].x + v[j].y * v[j].y + v[j].z * v[j].z + v[j].w * v[j].w;
    }
#pragma unroll
    for (int o = 16; o > 0; o >>= 1) {
        s1 += __shfl_xor_sync(0xffffffffu, s1, o);
        s2 += __shfl_xor_sync(0xffffffffu, s2, o);
    }
    const float mean = s1 * (1.0f / Z_DIM);
    const float var  = s2 * (1.0f / Z_DIM) - mean * mean;
    const float rstd = rsqrtf(var + LN_EPS);

    __half* orow = out + (size_t)row * Z_DIM;
#pragma unroll
    for (int j = 0; j < 8; j++) {
        int col = lane * 4 + j * 128;
        float4 g = *(const float4*)(gamma + col);
        float4 b = *(const float4*)(beta + col);
        __half2 h0 = __floats2half2_rn(fast_tanh((v[j].x - mean) * rstd * g.x + b.x),
                                       fast_tanh((v[j].y - mean) * rstd * g.y + b.y));
        __half2 h1 = __floats2half2_rn(fast_tanh((v[j].z - mean) * rstd * g.z + b.z),
                                       fast_tanh((v[j].w - mean) * rstd * g.w + b.w));
        uint2 o;
        o.x = *(uint32_t*)&h0; o.y = *(uint32_t*)&h1;
        *(uint2*)(orow + col) = o;
    }
}

// ---------------------------------------------------------------------------
extern "C" void kernel_launch(void* const* d_in, const int* in_sizes, int n_in,
                              void* d_out, int out_size)
{
    const float* x   = (const float*)d_in[0];
    const float* eps = (const float*)d_in[1];
    const float* W1  = (const float*)d_in[2];
    const float* b1  = (const float*)d_in[3];
    const float* g1  = (const float*)d_in[4];
    const float* be1 = (const float*)d_in[5];
    const float* W2  = (const float*)d_in[6];
    const float* b2  = (const float*)d_in[7];
    const float* g2  = (const float*)d_in[8];
    const float* be2 = (const float*)d_in[9];
    const float* Wmu = (const float*)d_in[10];
    const float* bmu = (const float*)d_in[11];
    const float* Wls = (const float*)d_in[12];
    const float* bls = (const float*)d_in[13];
    const float* Wzw = (const float*)d_in[14];
    const float* bzw = (const float*)d_in[15];

    float* out_p = (float*)d_out;
    float* mu_p  = out_p + MU_OFF;
    float* std_p = out_p + STD_OFF;

    float*  c_p;   cudaGetSymbolAddress((void**)&c_p,   g_c);
    __half* h_p;   cudaGetSymbolAddress((void**)&h_p,   g_h);
    __half* cat_p; cudaGetSymbolAddress((void**)&cat_p, g_cat);
    __half* x16_p; cudaGetSymbolAddress((void**)&x16_p, g_x16);
    __half* w_p;   cudaGetSymbolAddress((void**)&w_p,   g_w16);

    cudaFuncSetAttribute(gemm_f16_kernel,
                         cudaFuncAttributeMaxDynamicSharedMemorySize, GEMM_SMEM);

    dim3 blk(256);
    dim3 gblk(512);

    // 0) converts: x (+ tanh(x) into cat) ; all five weights in ONE launch
    {
        size_t nx8 = (size_t)M_TOK * D_IN / 8;
        x_prep_kernel<<<(unsigned)((nx8 + 255) / 256), blk>>>(x, x16_p, cat_p, nx8);
        wcvt_kernel<<<WCVT_BLOCKS, blk>>>(W1, W2, Wmu, Wls, Wzw, w_p);
    }

    // 1) c = x @ W1^T + b1
    gemm_f16_kernel<<<dim3(Z_DIM / 128, M_TOK / 256), gblk, GEMM_SMEM>>>(
        x16_p, w_p + W1_OFF, b1, nullptr, c_p, nullptr, nullptr, nullptr,
        M_TOK, Z_DIM, D_IN, 0);
    // 2) h = tanh(LN(c))   (warp-per-row)
    ln_tanh_kernel<<<M_TOK / 8, blk>>>(c_p, g1, be1, h_p);
    // 3) c = h @ W2^T + b2
    gemm_f16_kernel<<<dim3(Z_DIM / 128, M_TOK / 256), gblk, GEMM_SMEM>>>(
        h_p, w_p + W2_OFF, b2, nullptr, c_p, nullptr, nullptr, nullptr,
        M_TOK, Z_DIM, Z_DIM, 0);
    // 4) h = tanh(LN(c))
    ln_tanh_kernel<<<M_TOK / 8, blk>>>(c_p, g2, be2, h_p);
    // 5+6+7) fused: interleaved [mu|ls] GEMM -> mu, std, cat[:, :Z] in epilogue
    gemm_f16_kernel<<<dim3(2 * Z_DIM / 128, M_TOK / 256), gblk, GEMM_SMEM>>>(
        h_p, w_p + WMU_OFF, bmu, bls, mu_p, std_p, eps, cat_p,
        M_TOK, 2 * Z_DIM, Z_DIM, 3);
    // 8) out = cat @ Wzw^T + bzw
    gemm_f16_kernel<<<dim3(D_OUT / 128, M_TOK / 256), gblk, GEMM_SMEM>>>(
        cat_p, w_p + WZW_OFF, bzw, nullptr, out_p, nullptr, nullptr, nullptr,
        M_TOK, D_OUT, CAT_DIM, 0);
}

// round 16
// speedup vs baseline: 1.0323x; 1.0323x over previous
#include <cuda_runtime.h>
#include <cuda_fp16.h>
#include <math.h>
#include <stdint.h>

// Problem constants
#define M_TOK   8192
#define D_IN    4096
#define Z_DIM   1024
#define D_OUT   4096
#define CAT_DIM 5120
#define LN_EPS  1e-5f

#define MU_OFF  (M_TOK * (size_t)D_OUT)
#define STD_OFF (MU_OFF + (size_t)M_TOK * Z_DIM)

// Scratch (device globals — allocation-free per harness rules)
__device__ __align__(256) float  g_c[(size_t)M_TOK * Z_DIM];      // pre-LN (fp32)
__device__ __align__(256) __half g_h[(size_t)M_TOK * Z_DIM];      // post LN+tanh (fp16)
__device__ __align__(256) __half g_cat[(size_t)M_TOK * CAT_DIM];  // tanh concat (fp16)
__device__ __align__(256) __half g_x16[(size_t)M_TOK * D_IN];     // x in fp16
// fp16 weights, packed: W1 | W2 | Wmu | Wls | Wzw (Wmu,Wls adjacent => fused)
#define W1_OFF  0
#define W2_OFF  4194304
#define WMU_OFF 5242880
#define WLS_OFF 6291456
#define WZW_OFF 7340032
#define W_TOTAL 28311552
__device__ __align__(256) __half g_w16[(size_t)W_TOTAL];

// ---------------------------------------------------------------------------
// PTX helpers
// ---------------------------------------------------------------------------
__device__ __forceinline__ void cp16(uint32_t dst, const void* src) {
    asm volatile("cp.async.cg.shared.global [%0], [%1], 16;\n" :: "r"(dst), "l"(src));
}
__device__ __forceinline__ void cp_commit() {
    asm volatile("cp.async.commit_group;\n" ::: "memory");
}
__device__ __forceinline__ void cp_wait2() {
    asm volatile("cp.async.wait_group 2;\n" ::: "memory");
}
__device__ __forceinline__ void ldsm4(uint32_t* r, uint32_t addr) {
    asm volatile("ldmatrix.sync.aligned.m8n8.x4.shared.b16 {%0,%1,%2,%3}, [%4];\n"
        : "=r"(r[0]), "=r"(r[1]), "=r"(r[2]), "=r"(r[3]) : "r"(addr));
}
__device__ __forceinline__ void mma_f16(float* d, const uint32_t* a, const uint32_t* b) {
    asm volatile(
        "mma.sync.aligned.m16n8k16.row.col.f32.f16.f16.f32 "
        "{%0,%1,%2,%3}, {%4,%5,%6,%7}, {%8,%9}, {%0,%1,%2,%3};\n"
        : "+f"(d[0]), "+f"(d[1]), "+f"(d[2]), "+f"(d[3])
        : "r"(a[0]), "r"(a[1]), "r"(a[2]), "r"(a[3]), "r"(b[0]), "r"(b[1]));
}

// ---------------------------------------------------------------------------
// fp16 tensor-core GEMM (R9/R12/R13-verified geometry — do not touch):
// C[M,N](fp32) = A[M,K](fp16) * B[N,K]^T(fp16) + bias
// Block tile 256x128, BK=32 halfs, 4-stage cp.async, single sync per k-tile,
// 512 threads, 16 warps (4M x 4N), warp tile 64x32.
// mode 0: plain. mode 2: split N at Z_DIM -> C(+biasA) | exp(0.5*(v+biasB))->C2.
// ---------------------------------------------------------------------------
#define GBK 32
#define STAGE_BYTES 24576
#define B_OFF       16384
#define STAGES      4
#define GEMM_SMEM   (STAGES * STAGE_BYTES)    // 96 KB

__global__ void __launch_bounds__(512, 1)
gemm_f16_kernel(const __half* __restrict__ A, const __half* __restrict__ B,
                const float* __restrict__ biasA, const float* __restrict__ biasB,
                float* __restrict__ C, float* __restrict__ C2,
                int M, int N, int K, int mode)
{
    extern __shared__ __align__(128) char smem[];

    const int tid  = threadIdx.x;
    const int lane = tid & 31;
    const int warp = tid >> 5;
    const int warp_m = warp & 3;
    const int warp_n = warp >> 2;

    const int bm = blockIdx.y * 256;
    const int bn = blockIdx.x * 128;

    const uint32_t sm_base = (uint32_t)__cvta_generic_to_shared(smem);

    const int a_row = tid >> 1;
    const int a_c0  = (tid & 1) * 2;
    const int a_swz = (a_row >> 1) & 3;
    const __half* Ag = A + (size_t)(bm + a_row) * K + a_c0 * 8;
    uint32_t a_dst[2];
#pragma unroll
    for (int i = 0; i < 2; i++)
        a_dst[i] = sm_base + (uint32_t)(a_row * 64 + (((a_c0 + i) ^ a_swz) << 4));
    const int b_row = tid >> 2;
    const int b_c   = tid & 3;
    const int b_swz = (b_row >> 1) & 3;
    const __half* Bg = B + (size_t)(bn + b_row) * K + b_c * 8;
    const uint32_t b_dst = sm_base + B_OFF +
        (uint32_t)(b_row * 64 + ((b_c ^ b_swz) << 4));

    const int sa   = (lane & 7) + ((lane >> 3) & 1) * 8;
    const int hiA  = (lane >> 4) & 1;
    const int aswz = (sa >> 1) & 3;
    uint32_t a_base[4];
#pragma unroll
    for (int mf = 0; mf < 4; mf++)
        a_base[mf] = sm_base + (uint32_t)(warp_m * 64 + mf * 16 + sa) * 64u;

    const int hiB  = (lane >> 3) & 1;
    const int nbr  = ((lane >> 4) & 1) * 8 + (lane & 7);
    const int bswz = (nbr >> 1) & 3;
    uint32_t b_base[2];
#pragma unroll
    for (int p = 0; p < 2; p++)
        b_base[p] = sm_base + B_OFF + (uint32_t)(warp_n * 32 + p * 16 + nbr) * 64u;

    const float* bp = biasA;
    float* Cp = C;
    int cadj = 0, effN = N, emode = 0;
    if (mode == 2) {
        effN = Z_DIM;
        if (bn >= Z_DIM) { bp = biasB; Cp = C2; cadj = Z_DIM; emode = 1; }
    }

    float bias2[4][2];
#pragma unroll
    for (int nf = 0; nf < 4; nf++) {
        int col = bn - cadj + warp_n * 32 + nf * 8 + (lane & 3) * 2;
        bias2[nf][0] = __ldg(bp + col);
        bias2[nf][1] = __ldg(bp + col + 1);
    }

    float acc[4][4][4];
#pragma unroll
    for (int mf = 0; mf < 4; mf++)
#pragma unroll
        for (int nf = 0; nf < 4; nf++)
#pragma unroll
            for (int r = 0; r < 4; r++) acc[mf][nf][r] = 0.f;

    const int KT = K / GBK;

#pragma unroll
    for (int s = 0; s < STAGES - 1; s++) {
        if (s < KT) {
            const __half* ap = Ag + s * GBK;
            const __half* bq = Bg + s * GBK;
            uint32_t so = (uint32_t)s * STAGE_BYTES;
            cp16(a_dst[0] + so, ap);
            cp16(a_dst[1] + so, ap + 8);
            cp16(b_dst + so, bq);
        }
        cp_commit();
    }

    for (int kt = 0; kt < KT; kt++) {
        cp_wait2();
        __syncthreads();

        {
            int nxt = kt + (STAGES - 1);
            if (nxt < KT) {
                int sn = nxt & (STAGES - 1);
                const __half* ap = Ag + nxt * GBK;
                const __half* bq = Bg + nxt * GBK;
                uint32_t so = (uint32_t)sn * STAGE_BYTES;
                cp16(a_dst[0] + so, ap);
                cp16(a_dst[1] + so, ap + 8);
                cp16(b_dst + so, bq);
            }
            cp_commit();
        }

        const uint32_t so = (uint32_t)(kt & (STAGES - 1)) * STAGE_BYTES;
#pragma unroll
        for (int kk = 0; kk < 2; kk++) {
            uint32_t a[4][4];
#pragma unroll
            for (int mf = 0; mf < 4; mf++)
                ldsm4(a[mf], a_base[mf] + so + (uint32_t)(((kk * 2 + hiA) ^ aswz) << 4));
            uint32_t b[4][2];
#pragma unroll
            for (int p = 0; p < 2; p++) {
                uint32_t r[4];
                ldsm4(r, b_base[p] + so + (uint32_t)(((kk * 2 + hiB) ^ bswz) << 4));
                b[2 * p][0] = r[0]; b[2 * p][1] = r[1];
                b[2 * p + 1][0] = r[2]; b[2 * p + 1][1] = r[3];
            }
#pragma unroll
            for (int mf = 0; mf < 4; mf++)
#pragma unroll
                for (int nf = 0; nf < 4; nf++)
                    mma_f16(acc[mf][nf], a[mf], b[nf]);
        }
    }

#pragma unroll
    for (int mf = 0; mf < 4; mf++) {
        int r0 = bm + warp_m * 64 + mf * 16 + (lane >> 2);
#pragma unroll
        for (int nf = 0; nf < 4; nf++) {
            int col = bn - cadj + warp_n * 32 + nf * 8 + (lane & 3) * 2;
            float v0 = acc[mf][nf][0] + bias2[nf][0];
            float v1 = acc[mf][nf][1] + bias2[nf][1];
            float v2 = acc[mf][nf][2] + bias2[nf][0];
            float v3 = acc[mf][nf][3] + bias2[nf][1];
            if (emode == 1) {
                v0 = expf(0.5f * v0); v1 = expf(0.5f * v1);
                v2 = expf(0.5f * v2); v3 = expf(0.5f * v3);
            }
            *(float2*)(Cp + (size_t)r0 * effN + col) = make_float2(v0, v1);
            *(float2*)(Cp + (size_t)(r0 + 8) * effN + col) = make_float2(v2, v3);
        }
    }
}

// ---------------------------------------------------------------------------
// x prep: x16 = fp16(x) AND cat[:,Z_DIM:] = fp16(tanh(x)). 8 elems/thread.
// ---------------------------------------------------------------------------
__global__ void __launch_bounds__(256)
x_prep_kernel(const float* __restrict__ x, __half* __restrict__ x16,
              __half* __restrict__ cat, size_t n8)
{
    size_t i = (size_t)blockIdx.x * blockDim.x + threadIdx.x;
    if (i >= n8) return;
    size_t e = i * 8;
    float4 v0 = *(const float4*)(x + e);
    float4 v1 = *(const float4*)(x + e + 4);
    __half2 h0 = __floats2half2_rn(v0.x, v0.y);
    __half2 h1 = __floats2half2_rn(v0.z, v0.w);
    __half2 h2 = __floats2half2_rn(v1.x, v1.y);
    __half2 h3 = __floats2half2_rn(v1.z, v1.w);
    uint4 o;
    o.x = *(uint32_t*)&h0; o.y = *(uint32_t*)&h1;
    o.z = *(uint32_t*)&h2; o.w = *(uint32_t*)&h3;
    *(uint4*)(x16 + e) = o;

    __half2 t0 = __floats2half2_rn(tanhf(v0.x), tanhf(v0.y));
    __half2 t1 = __floats2half2_rn(tanhf(v0.z), tanhf(v0.w));
    __half2 t2 = __floats2half2_rn(tanhf(v1.x), tanhf(v1.y));
    __half2 t3 = __floats2half2_rn(tanhf(v1.z), tanhf(v1.w));
    uint4 t;
    t.x = *(uint32_t*)&t0; t.y = *(uint32_t*)&t1;
    t.z = *(uint32_t*)&t2; t.w = *(uint32_t*)&t3;
    size_t row = e >> 12;                 // / D_IN
    int col = (int)(e & (D_IN - 1));
    *(uint4*)(cat + row * CAT_DIM + Z_DIM + col) = t;
}

// ---------------------------------------------------------------------------
// Segmented weight convert: one launch handles W1|W2|Wmu|Wls|Wzw (fp32->fp16).
// Block ranges (256 thr x 8 elems = 2048 elems/block).
// ---------------------------------------------------------------------------
#define WCVT_BLOCKS 13824

__global__ void __launch_bounds__(256)
wcvt_kernel(const float* __restrict__ W1, const float* __restrict__ W2,
            const float* __restrict__ Wmu, const float* __restrict__ Wls,
            const float* __restrict__ Wzw, __half* __restrict__ w16)
{
    int bid = blockIdx.x;
    const float* src;
    __half* dst;
    int lb;
    if (bid < 2048)      { src = W1;  dst = w16 + W1_OFF;  lb = bid; }
    else if (bid < 2560) { src = W2;  dst = w16 + W2_OFF;  lb = bid - 2048; }
    else if (bid < 3072) { src = Wmu; dst = w16 + WMU_OFF; lb = bid - 2560; }
    else if (bid < 3584) { src = Wls; dst = w16 + WLS_OFF; lb = bid - 3072; }
    else                 { src = Wzw; dst = w16 + WZW_OFF; lb = bid - 3584; }

    size_t e = ((size_t)lb * 256 + threadIdx.x) * 8;
    float4 v0 = *(const float4*)(src + e);
    float4 v1 = *(const float4*)(src + e + 4);
    __half2 h0 = __floats2half2_rn(v0.x, v0.y);
    __half2 h1 = __floats2half2_rn(v0.z, v0.w);
    __half2 h2 = __floats2half2_rn(v1.x, v1.y);
    __half2 h3 = __floats2half2_rn(v1.z, v1.w);
    uint4 o;
    o.x = *(uint32_t*)&h0; o.y = *(uint32_t*)&h1;
    o.z = *(uint32_t*)&h2; o.w = *(uint32_t*)&h3;
    *(uint4*)(dst + e) = o;
}

// ---------------------------------------------------------------------------
// LayerNorm (1024) + tanh, single-pass (E[x^2]-mu^2), fp32 in -> fp16 out.
// (R13-verified: block-per-row, 256 threads, two shuffle cascades.)
// ---------------------------------------------------------------------------
__global__ void __launch_bounds__(256)
ln_tanh_kernel(const float* __restrict__ in, const float* __restrict__ gamma,
               const float* __restrict__ beta, __half* __restrict__ out)
{
    const int row = blockIdx.x;
    const int tid = threadIdx.x;
    const float* p = in + (size_t)row * Z_DIM;

    float4 v = *(const float4*)(p + tid * 4);

    float s1 = v.x + v.y + v.z + v.w;
    float s2 = v.x * v.x + v.y * v.y + v.z * v.z + v.w * v.w;

    __shared__ float red1[8], red2[8];
#pragma unroll
    for (int o = 16; o > 0; o >>= 1) {
        s1 += __shfl_down_sync(0xffffffffu, s1, o);
        s2 += __shfl_down_sync(0xffffffffu, s2, o);
    }
    if ((tid & 31) == 0) { red1[tid >> 5] = s1; red2[tid >> 5] = s2; }
    __syncthreads();
    {
        float t1 = (tid < 8) ? red1[tid] : 0.f;
        float t2 = (tid < 8) ? red2[tid] : 0.f;
#pragma unroll
        for (int o = 4; o > 0; o >>= 1) {
            t1 += __shfl_down_sync(0xffu, t1, o);
            t2 += __shfl_down_sync(0xffu, t2, o);
        }
        if (tid == 0) { red1[0] = t1; red2[0] = t2; }
    }
    __syncthreads();
    const float mean = red1[0] * (1.0f / Z_DIM);
    const float var  = red2[0] * (1.0f / Z_DIM) - mean * mean;
    const float rstd = rsqrtf(var + LN_EPS);

    const int col = tid * 4;
    float4 g = *(const float4*)(gamma + col);
    float4 b = *(const float4*)(beta + col);
    float d0 = v.x - mean, d1 = v.y - mean, d2 = v.z - mean, d3 = v.w - mean;
    __half2 h0 = __floats2half2_rn(tanhf(d0 * rstd * g.x + b.x),
                                   tanhf(d1 * rstd * g.y + b.y));
    __half2 h1 = __floats2half2_rn(tanhf(d2 * rstd * g.z + b.z),
                                   tanhf(d3 * rstd * g.w + b.w));
    uint2 o;
    o.x = *(uint32_t*)&h0; o.y = *(uint32_t*)&h1;
    *(uint2*)(out + (size_t)row * Z_DIM + col) = o;
}

// ---------------------------------------------------------------------------
// z-part of cat: cat[:, :Z_DIM] = fp16(tanh(eps*std+mu)). 4 elems/thread,
// float4 loads (vectorized vs R13's 2-elem version).
// ---------------------------------------------------------------------------
__global__ void __launch_bounds__(256)
cat_z_kernel(const float* __restrict__ eps, const float* __restrict__ mu,
             const float* __restrict__ stdv, __half* __restrict__ cat)
{
    size_t idx = (size_t)blockIdx.x * blockDim.x + threadIdx.x;
    size_t total4 = (size_t)M_TOK * Z_DIM / 4;
    if (idx >= total4) return;
    size_t row = idx >> 8;                 // / (Z_DIM/4)
    int col = (int)(idx & 255) * 4;
    size_t zi = row * Z_DIM + col;
    float4 e = *(const float4*)(eps + zi);
    float4 m = *(const float4*)(mu + zi);
    float4 s = *(const float4*)(stdv + zi);
    __half2 h0 = __floats2half2_rn(tanhf(e.x * s.x + m.x), tanhf(e.y * s.y + m.y));
    __half2 h1 = __floats2half2_rn(tanhf(e.z * s.z + m.z), tanhf(e.w * s.w + m.w));
    uint2 o;
    o.x = *(uint32_t*)&h0; o.y = *(uint32_t*)&h1;
    *(uint2*)(cat + row * CAT_DIM + col) = o;
}

// ---------------------------------------------------------------------------
extern "C" void kernel_launch(void* const* d_in, const int* in_sizes, int n_in,
                              void* d_out, int out_size)
{
    const float* x   = (const float*)d_in[0];
    const float* eps = (const float*)d_in[1];
    const float* W1  = (const float*)d_in[2];
    const float* b1  = (const float*)d_in[3];
    const float* g1  = (const float*)d_in[4];
    const float* be1 = (const float*)d_in[5];
    const float* W2  = (const float*)d_in[6];
    const float* b2  = (const float*)d_in[7];
    const float* g2  = (const float*)d_in[8];
    const float* be2 = (const float*)d_in[9];
    const float* Wmu = (const float*)d_in[10];
    const float* bmu = (const float*)d_in[11];
    const float* Wls = (const float*)d_in[12];
    const float* bls = (const float*)d_in[13];
    const float* Wzw = (const float*)d_in[14];
    const float* bzw = (const float*)d_in[15];

    float* out_p = (float*)d_out;
    float* mu_p  = out_p + MU_OFF;
    float* std_p = out_p + STD_OFF;

    float*  c_p;   cudaGetSymbolAddress((void**)&c_p,   g_c);
    __half* h_p;   cudaGetSymbolAddress((void**)&h_p,   g_h);
    __half* cat_p; cudaGetSymbolAddress((void**)&cat_p, g_cat);
    __half* x16_p; cudaGetSymbolAddress((void**)&x16_p, g_x16);
    __half* w_p;   cudaGetSymbolAddress((void**)&w_p,   g_w16);

    cudaFuncSetAttribute(gemm_f16_kernel,
                         cudaFuncAttributeMaxDynamicSharedMemorySize, GEMM_SMEM);

    dim3 blk(256);
    dim3 gblk(512);

    // 0) converts: x (+ tanh(x) into cat) ; all five weights in ONE launch
    {
        size_t nx8 = (size_t)M_TOK * D_IN / 8;
        x_prep_kernel<<<(unsigned)((nx8 + 255) / 256), blk>>>(x, x16_p, cat_p, nx8);
        wcvt_kernel<<<WCVT_BLOCKS, blk>>>(W1, W2, Wmu, Wls, Wzw, w_p);
    }

    // 1) c = x @ W1^T + b1
    gemm_f16_kernel<<<dim3(Z_DIM / 128, M_TOK / 256), gblk, GEMM_SMEM>>>(
        x16_p, w_p + W1_OFF, b1, nullptr, c_p, nullptr, M_TOK, Z_DIM, D_IN, 0);
    // 2) h = tanh(LN(c))
    ln_tanh_kernel<<<M_TOK, blk>>>(c_p, g1, be1, h_p);
    // 3) c = h @ W2^T + b2
    gemm_f16_kernel<<<dim3(Z_DIM / 128, M_TOK / 256), gblk, GEMM_SMEM>>>(
        h_p, w_p + W2_OFF, b2, nullptr, c_p, nullptr, M_TOK, Z_DIM, Z_DIM, 0);
    // 4) h = tanh(LN(c))
    ln_tanh_kernel<<<M_TOK, blk>>>(c_p, g2, be2, h_p);
    // 5+6) fused: [mu | std] = h @ [Wmu|Wls]^T  (std half gets exp(0.5*..))
    gemm_f16_kernel<<<dim3(2 * Z_DIM / 128, M_TOK / 256), gblk, GEMM_SMEM>>>(
        h_p, w_p + WMU_OFF, bmu, bls, mu_p, std_p, M_TOK, 2 * Z_DIM, Z_DIM, 2);
    // 7) cat z-part (x-part already written by x_prep)
    {
        size_t total4 = (size_t)M_TOK * Z_DIM / 4;
        cat_z_kernel<<<(unsigned)((total4 + 255) / 256), blk>>>(eps, mu_p, std_p, cat_p);
    }
    // 8) out = cat @ Wzw^T + bzw
    gemm_f16_kernel<<<dim3(D_OUT / 128, M_TOK / 256), gblk, GEMM_SMEM>>>(
        cat_p, w_p + WZW_OFF, bzw, nullptr, out_p, nullptr, M_TOK, D_OUT, CAT_DIM, 0);
}

// round 17
// speedup vs baseline: 1.0335x; 1.0012x over previous
#include <cuda_runtime.h>
#include <cuda_fp16.h>
#include <math.h>
#include <stdint.h>

// Problem constants
#define M_TOK   8192
#define D_IN    4096
#define Z_DIM   1024
#define D_OUT   4096
#define CAT_DIM 5120
#define LN_EPS  1e-5f

#define MU_OFF  (M_TOK * (size_t)D_OUT)
#define STD_OFF (MU_OFF + (size_t)M_TOK * Z_DIM)

// Scratch (device globals — allocation-free per harness rules)
__device__ __align__(256) float  g_c[(size_t)M_TOK * Z_DIM];      // pre-LN (fp32)
__device__ __align__(256) __half g_h[(size_t)M_TOK * Z_DIM];      // post LN+tanh (fp16)
__device__ __align__(256) __half g_cat[(size_t)M_TOK * CAT_DIM];  // tanh concat (fp16)
__device__ __align__(256) __half g_x16[(size_t)M_TOK * D_IN];     // x in fp16
// fp16 weights, packed: W1 | W2 | Wmu | Wls | Wzw (Wmu,Wls adjacent => fused)
#define W1_OFF  0
#define W2_OFF  4194304
#define WMU_OFF 5242880
#define WLS_OFF 6291456
#define WZW_OFF 7340032
#define W_TOTAL 28311552
__device__ __align__(256) __half g_w16[(size_t)W_TOTAL];

// ---------------------------------------------------------------------------
// PTX helpers
// ---------------------------------------------------------------------------
__device__ __forceinline__ void cp16(uint32_t dst, const void* src) {
    asm volatile("cp.async.cg.shared.global [%0], [%1], 16;\n" :: "r"(dst), "l"(src));
}
__device__ __forceinline__ void cp_commit() {
    asm volatile("cp.async.commit_group;\n" ::: "memory");
}
__device__ __forceinline__ void cp_wait2() {
    asm volatile("cp.async.wait_group 2;\n" ::: "memory");
}
__device__ __forceinline__ void ldsm4(uint32_t* r, uint32_t addr) {
    asm volatile("ldmatrix.sync.aligned.m8n8.x4.shared.b16 {%0,%1,%2,%3}, [%4];\n"
        : "=r"(r[0]), "=r"(r[1]), "=r"(r[2]), "=r"(r[3]) : "r"(addr));
}
__device__ __forceinline__ void mma_f16(float* d, const uint32_t* a, const uint32_t* b) {
    asm volatile(
        "mma.sync.aligned.m16n8k16.row.col.f32.f16.f16.f32 "
        "{%0,%1,%2,%3}, {%4,%5,%6,%7}, {%8,%9}, {%0,%1,%2,%3};\n"
        : "+f"(d[0]), "+f"(d[1]), "+f"(d[2]), "+f"(d[3])
        : "r"(a[0]), "r"(a[1]), "r"(a[2]), "r"(a[3]), "r"(b[0]), "r"(b[1]));
}

// ---------------------------------------------------------------------------
// fp16 tensor-core GEMM (R9/R12/R13/R16-verified geometry — do not touch):
// C[M,N](fp32) = A[M,K](fp16) * B[N,K]^T(fp16) + bias
// Block tile 256x128, BK=32 halfs, 4-stage cp.async, single sync per k-tile,
// 512 threads, 16 warps (4M x 4N), warp tile 64x32.
// mode 0: plain. mode 2: split N at Z_DIM -> C(+biasA) | exp(0.5*(v+biasB))->C2.
// ---------------------------------------------------------------------------
#define GBK 32
#define STAGE_BYTES 24576
#define B_OFF       16384
#define STAGES      4
#define GEMM_SMEM   (STAGES * STAGE_BYTES)    // 96 KB

__global__ void __launch_bounds__(512, 1)
gemm_f16_kernel(const __half* __restrict__ A, const __half* __restrict__ B,
                const float* __restrict__ biasA, const float* __restrict__ biasB,
                float* __restrict__ C, float* __restrict__ C2,
                int M, int N, int K, int mode)
{
    extern __shared__ __align__(128) char smem[];

    const int tid  = threadIdx.x;
    const int lane = tid & 31;
    const int warp = tid >> 5;
    const int warp_m = warp & 3;
    const int warp_n = warp >> 2;

    const int bm = blockIdx.y * 256;
    const int bn = blockIdx.x * 128;

    const uint32_t sm_base = (uint32_t)__cvta_generic_to_shared(smem);

    const int a_row = tid >> 1;
    const int a_c0  = (tid & 1) * 2;
    const int a_swz = (a_row >> 1) & 3;
    const __half* Ag = A + (size_t)(bm + a_row) * K + a_c0 * 8;
    uint32_t a_dst[2];
#pragma unroll
    for (int i = 0; i < 2; i++)
        a_dst[i] = sm_base + (uint32_t)(a_row * 64 + (((a_c0 + i) ^ a_swz) << 4));
    const int b_row = tid >> 2;
    const int b_c   = tid & 3;
    const int b_swz = (b_row >> 1) & 3;
    const __half* Bg = B + (size_t)(bn + b_row) * K + b_c * 8;
    const uint32_t b_dst = sm_base + B_OFF +
        (uint32_t)(b_row * 64 + ((b_c ^ b_swz) << 4));

    const int sa   = (lane & 7) + ((lane >> 3) & 1) * 8;
    const int hiA  = (lane >> 4) & 1;
    const int aswz = (sa >> 1) & 3;
    uint32_t a_base[4];
#pragma unroll
    for (int mf = 0; mf < 4; mf++)
        a_base[mf] = sm_base + (uint32_t)(warp_m * 64 + mf * 16 + sa) * 64u;

    const int hiB  = (lane >> 3) & 1;
    const int nbr  = ((lane >> 4) & 1) * 8 + (lane & 7);
    const int bswz = (nbr >> 1) & 3;
    uint32_t b_base[2];
#pragma unroll
    for (int p = 0; p < 2; p++)
        b_base[p] = sm_base + B_OFF + (uint32_t)(warp_n * 32 + p * 16 + nbr) * 64u;

    const float* bp = biasA;
    float* Cp = C;
    int cadj = 0, effN = N, emode = 0;
    if (mode == 2) {
        effN = Z_DIM;
        if (bn >= Z_DIM) { bp = biasB; Cp = C2; cadj = Z_DIM; emode = 1; }
    }

    float bias2[4][2];
#pragma unroll
    for (int nf = 0; nf < 4; nf++) {
        int col = bn - cadj + warp_n * 32 + nf * 8 + (lane & 3) * 2;
        bias2[nf][0] = __ldg(bp + col);
        bias2[nf][1] = __ldg(bp + col + 1);
    }

    float acc[4][4][4];
#pragma unroll
    for (int mf = 0; mf < 4; mf++)
#pragma unroll
        for (int nf = 0; nf < 4; nf++)
#pragma unroll
            for (int r = 0; r < 4; r++) acc[mf][nf][r] = 0.f;

    const int KT = K / GBK;

#pragma unroll
    for (int s = 0; s < STAGES - 1; s++) {
        if (s < KT) {
            const __half* ap = Ag + s * GBK;
            const __half* bq = Bg + s * GBK;
            uint32_t so = (uint32_t)s * STAGE_BYTES;
            cp16(a_dst[0] + so, ap);
            cp16(a_dst[1] + so, ap + 8);
            cp16(b_dst + so, bq);
        }
        cp_commit();
    }

    for (int kt = 0; kt < KT; kt++) {
        cp_wait2();
        __syncthreads();

        {
            int nxt = kt + (STAGES - 1);
            if (nxt < KT) {
                int sn = nxt & (STAGES - 1);
                const __half* ap = Ag + nxt * GBK;
                const __half* bq = Bg + nxt * GBK;
                uint32_t so = (uint32_t)sn * STAGE_BYTES;
                cp16(a_dst[0] + so, ap);
                cp16(a_dst[1] + so, ap + 8);
                cp16(b_dst + so, bq);
            }
            cp_commit();
        }

        const uint32_t so = (uint32_t)(kt & (STAGES - 1)) * STAGE_BYTES;
#pragma unroll
        for (int kk = 0; kk < 2; kk++) {
            uint32_t a[4][4];
#pragma unroll
            for (int mf = 0; mf < 4; mf++)
                ldsm4(a[mf], a_base[mf] + so + (uint32_t)(((kk * 2 + hiA) ^ aswz) << 4));
            uint32_t b[4][2];
#pragma unroll
            for (int p = 0; p < 2; p++) {
                uint32_t r[4];
                ldsm4(r, b_base[p] + so + (uint32_t)(((kk * 2 + hiB) ^ bswz) << 4));
                b[2 * p][0] = r[0]; b[2 * p][1] = r[1];
                b[2 * p + 1][0] = r[2]; b[2 * p + 1][1] = r[3];
            }
#pragma unroll
            for (int mf = 0; mf < 4; mf++)
#pragma unroll
                for (int nf = 0; nf < 4; nf++)
                    mma_f16(acc[mf][nf], a[mf], b[nf]);
        }
    }

#pragma unroll
    for (int mf = 0; mf < 4; mf++) {
        int r0 = bm + warp_m * 64 + mf * 16 + (lane >> 2);
#pragma unroll
        for (int nf = 0; nf < 4; nf++) {
            int col = bn - cadj + warp_n * 32 + nf * 8 + (lane & 3) * 2;
            float v0 = acc[mf][nf][0] + bias2[nf][0];
            float v1 = acc[mf][nf][1] + bias2[nf][1];
            float v2 = acc[mf][nf][2] + bias2[nf][0];
            float v3 = acc[mf][nf][3] + bias2[nf][1];
            if (emode == 1) {
                v0 = __expf(0.5f * v0); v1 = __expf(0.5f * v1);
                v2 = __expf(0.5f * v2); v3 = __expf(0.5f * v3);
            }
            *(float2*)(Cp + (size_t)r0 * effN + col) = make_float2(v0, v1);
            *(float2*)(Cp + (size_t)(r0 + 8) * effN + col) = make_float2(v2, v3);
        }
    }
}

// ---------------------------------------------------------------------------
// Unified prep kernel: ONE launch for all input conversion.
//   blocks [0, 16384)       : x -> x16 (fp16) AND cat[:,Z_DIM:] = fp16(tanh(x))
//   blocks [16384, 18432)   : W1  -> fp16
//   blocks [18432, 18944)   : W2  -> fp16
//   blocks [18944, 19456)   : Wmu -> fp16
//   blocks [19456, 19968)   : Wls -> fp16
//   blocks [19968, 30208)   : Wzw -> fp16
// 256 threads x 8 elems = 2048 elems/block everywhere.
// ---------------------------------------------------------------------------
#define XPREP_BLOCKS 16384
#define PREP_BLOCKS  30208

__global__ void __launch_bounds__(256)
prep_kernel(const float* __restrict__ x,
            const float* __restrict__ W1, const float* __restrict__ W2,
            const float* __restrict__ Wmu, const float* __restrict__ Wls,
            const float* __restrict__ Wzw,
            __half* __restrict__ x16, __half* __restrict__ cat,
            __half* __restrict__ w16)
{
    const int bid = blockIdx.x;

    if (bid < XPREP_BLOCKS) {
        size_t e = ((size_t)bid * 256 + threadIdx.x) * 8;
        float4 v0 = *(const float4*)(x + e);
        float4 v1 = *(const float4*)(x + e + 4);
        __half2 h0 = __floats2half2_rn(v0.x, v0.y);
        __half2 h1 = __floats2half2_rn(v0.z, v0.w);
        __half2 h2 = __floats2half2_rn(v1.x, v1.y);
        __half2 h3 = __floats2half2_rn(v1.z, v1.w);
        uint4 o;
        o.x = *(uint32_t*)&h0; o.y = *(uint32_t*)&h1;
        o.z = *(uint32_t*)&h2; o.w = *(uint32_t*)&h3;
        *(uint4*)(x16 + e) = o;

        __half2 t0 = __floats2half2_rn(tanhf(v0.x), tanhf(v0.y));
        __half2 t1 = __floats2half2_rn(tanhf(v0.z), tanhf(v0.w));
        __half2 t2 = __floats2half2_rn(tanhf(v1.x), tanhf(v1.y));
        __half2 t3 = __floats2half2_rn(tanhf(v1.z), tanhf(v1.w));
        uint4 t;
        t.x = *(uint32_t*)&t0; t.y = *(uint32_t*)&t1;
        t.z = *(uint32_t*)&t2; t.w = *(uint32_t*)&t3;
        size_t row = e >> 12;                 // / D_IN
        int col = (int)(e & (D_IN - 1));
        *(uint4*)(cat + row * CAT_DIM + Z_DIM + col) = t;
        return;
    }

    // weight conversion segments
    int wb = bid - XPREP_BLOCKS;
    const float* src;
    __half* dst;
    int lb;
    if (wb < 2048)      { src = W1;  dst = w16 + W1_OFF;  lb = wb; }
    else if (wb < 2560) { src = W2;  dst = w16 + W2_OFF;  lb = wb - 2048; }
    else if (wb < 3072) { src = Wmu; dst = w16 + WMU_OFF; lb = wb - 2560; }
    else if (wb < 3584) { src = Wls; dst = w16 + WLS_OFF; lb = wb - 3072; }
    else                { src = Wzw; dst = w16 + WZW_OFF; lb = wb - 3584; }

    size_t e = ((size_t)lb * 256 + threadIdx.x) * 8;
    float4 v0 = *(const float4*)(src + e);
    float4 v1 = *(const float4*)(src + e + 4);
    __half2 h0 = __floats2half2_rn(v0.x, v0.y);
    __half2 h1 = __floats2half2_rn(v0.z, v0.w);
    __half2 h2 = __floats2half2_rn(v1.x, v1.y);
    __half2 h3 = __floats2half2_rn(v1.z, v1.w);
    uint4 o;
    o.x = *(uint32_t*)&h0; o.y = *(uint32_t*)&h1;
    o.z = *(uint32_t*)&h2; o.w = *(uint32_t*)&h3;
    *(uint4*)(dst + e) = o;
}

// ---------------------------------------------------------------------------
// LayerNorm (1024) + tanh, single-pass (E[x^2]-mu^2), fp32 in -> fp16 out.
// (R13/R16-verified: block-per-row, 256 threads, two shuffle cascades.)
// ---------------------------------------------------------------------------
__global__ void __launch_bounds__(256)
ln_tanh_kernel(const float* __restrict__ in, const float* __restrict__ gamma,
               const float* __restrict__ beta, __half* __restrict__ out)
{
    const int row = blockIdx.x;
    const int tid = threadIdx.x;
    const float* p = in + (size_t)row * Z_DIM;

    float4 v = *(const float4*)(p + tid * 4);

    float s1 = v.x + v.y + v.z + v.w;
    float s2 = v.x * v.x + v.y * v.y + v.z * v.z + v.w * v.w;

    __shared__ float red1[8], red2[8];
#pragma unroll
    for (int o = 16; o > 0; o >>= 1) {
        s1 += __shfl_down_sync(0xffffffffu, s1, o);
        s2 += __shfl_down_sync(0xffffffffu, s2, o);
    }
    if ((tid & 31) == 0) { red1[tid >> 5] = s1; red2[tid >> 5] = s2; }
    __syncthreads();
    {
        float t1 = (tid < 8) ? red1[tid] : 0.f;
        float t2 = (tid < 8) ? red2[tid] : 0.f;
#pragma unroll
        for (int o = 4; o > 0; o >>= 1) {
            t1 += __shfl_down_sync(0xffu, t1, o);
            t2 += __shfl_down_sync(0xffu, t2, o);
        }
        if (tid == 0) { red1[0] = t1; red2[0] = t2; }
    }
    __syncthreads();
    const float mean = red1[0] * (1.0f / Z_DIM);
    const float var  = red2[0] * (1.0f / Z_DIM) - mean * mean;
    const float rstd = rsqrtf(var + LN_EPS);

    const int col = tid * 4;
    float4 g = *(const float4*)(gamma + col);
    float4 b = *(const float4*)(beta + col);
    float d0 = v.x - mean, d1 = v.y - mean, d2 = v.z - mean, d3 = v.w - mean;
    __half2 h0 = __floats2half2_rn(tanhf(d0 * rstd * g.x + b.x),
                                   tanhf(d1 * rstd * g.y + b.y));
    __half2 h1 = __floats2half2_rn(tanhf(d2 * rstd * g.z + b.z),
                                   tanhf(d3 * rstd * g.w + b.w));
    uint2 o;
    o.x = *(uint32_t*)&h0; o.y = *(uint32_t*)&h1;
    *(uint2*)(out + (size_t)row * Z_DIM + col) = o;
}

// ---------------------------------------------------------------------------
// z-part of cat: cat[:, :Z_DIM] = fp16(tanh(eps*std+mu)). 4 elems/thread,
// float4 loads.
// ---------------------------------------------------------------------------
__global__ void __launch_bounds__(256)
cat_z_kernel(const float* __restrict__ eps, const float* __restrict__ mu,
             const float* __restrict__ stdv, __half* __restrict__ cat)
{
    size_t idx = (size_t)blockIdx.x * blockDim.x + threadIdx.x;
    size_t total4 = (size_t)M_TOK * Z_DIM / 4;
    if (idx >= total4) return;
    size_t row = idx >> 8;                 // / (Z_DIM/4)
    int col = (int)(idx & 255) * 4;
    size_t zi = row * Z_DIM + col;
    float4 e = *(const float4*)(eps + zi);
    float4 m = *(const float4*)(mu + zi);
    float4 s = *(const float4*)(stdv + zi);
    __half2 h0 = __floats2half2_rn(tanhf(e.x * s.x + m.x), tanhf(e.y * s.y + m.y));
    __half2 h1 = __floats2half2_rn(tanhf(e.z * s.z + m.z), tanhf(e.w * s.w + m.w));
    uint2 o;
    o.x = *(uint32_t*)&h0; o.y = *(uint32_t*)&h1;
    *(uint2*)(cat + row * CAT_DIM + col) = o;
}

// ---------------------------------------------------------------------------
extern "C" void kernel_launch(void* const* d_in, const int* in_sizes, int n_in,
                              void* d_out, int out_size)
{
    const float* x   = (const float*)d_in[0];
    const float* eps = (const float*)d_in[1];
    const float* W1  = (const float*)d_in[2];
    const float* b1  = (const float*)d_in[3];
    const float* g1  = (const float*)d_in[4];
    const float* be1 = (const float*)d_in[5];
    const float* W2  = (const float*)d_in[6];
    const float* b2  = (const float*)d_in[7];
    const float* g2  = (const float*)d_in[8];
    const float* be2 = (const float*)d_in[9];
    const float* Wmu = (const float*)d_in[10];
    const float* bmu = (const float*)d_in[11];
    const float* Wls = (const float*)d_in[12];
    const float* bls = (const float*)d_in[13];
    const float* Wzw = (const float*)d_in[14];
    const float* bzw = (const float*)d_in[15];

    float* out_p = (float*)d_out;
    float* mu_p  = out_p + MU_OFF;
    float* std_p = out_p + STD_OFF;

    float*  c_p;   cudaGetSymbolAddress((void**)&c_p,   g_c);
    __half* h_p;   cudaGetSymbolAddress((void**)&h_p,   g_h);
    __half* cat_p; cudaGetSymbolAddress((void**)&cat_p, g_cat);
    __half* x16_p; cudaGetSymbolAddress((void**)&x16_p, g_x16);
    __half* w_p;   cudaGetSymbolAddress((void**)&w_p,   g_w16);

    cudaFuncSetAttribute(gemm_f16_kernel,
                         cudaFuncAttributeMaxDynamicSharedMemorySize, GEMM_SMEM);

    dim3 blk(256);
    dim3 gblk(512);

    // 0) ALL input conversion in one launch: x->x16, tanh(x)->cat, 5 weights
    prep_kernel<<<PREP_BLOCKS, blk>>>(x, W1, W2, Wmu, Wls, Wzw,
                                      x16_p, cat_p, w_p);

    // 1) c = x @ W1^T + b1
    gemm_f16_kernel<<<dim3(Z_DIM / 128, M_TOK / 256), gblk, GEMM_SMEM>>>(
        x16_p, w_p + W1_OFF, b1, nullptr, c_p, nullptr, M_TOK, Z_DIM, D_IN, 0);
    // 2) h = tanh(LN(c))
    ln_tanh_kernel<<<M_TOK, blk>>>(c_p, g1, be1, h_p);
    // 3) c = h @ W2^T + b2
    gemm_f16_kernel<<<dim3(Z_DIM / 128, M_TOK / 256), gblk, GEMM_SMEM>>>(
        h_p, w_p + W2_OFF, b2, nullptr, c_p, nullptr, M_TOK, Z_DIM, Z_DIM, 0);
    // 4) h = tanh(LN(c))
    ln_tanh_kernel<<<M_TOK, blk>>>(c_p, g2, be2, h_p);
    // 5+6) fused: [mu | std] = h @ [Wmu|Wls]^T  (std half gets exp(0.5*..))
    gemm_f16_kernel<<<dim3(2 * Z_DIM / 128, M_TOK / 256), gblk, GEMM_SMEM>>>(
        h_p, w_p + WMU_OFF, bmu, bls, mu_p, std_p, M_TOK, 2 * Z_DIM, Z_DIM, 2);
    // 7) cat z-part (x-part already written by prep)
    {
        size_t total4 = (size_t)M_TOK * Z_DIM / 4;
        cat_z_kernel<<<(unsigned)((total4 + 255) / 256), blk>>>(eps, mu_p, std_p, cat_p);
    }
    // 8) out = cat @ Wzw^T + bzw
    gemm_f16_kernel<<<dim3(D_OUT / 128, M_TOK / 256), gblk, GEMM_SMEM>>>(
        cat_p, w_p + WZW_OFF, bzw, nullptr, out_p, nullptr, M_TOK, D_OUT, CAT_DIM, 0);
}